// round 12
// baseline (speedup 1.0000x reference)
#include <cuda_runtime.h>

#define BB 64
#define II 512
#define HH 1024
#define NCHUNK 32              // h-dimension split for rec partials
#define HCHUNK (HH / NCHUNK)   // 32
#define BTILE 4                // batches per block in rec kernel
#define BGROUPS (BB / BTILE)   // 16
#define CROWS 8                // (b,h) rows per block in hebb update
#define CLIPV 2.0f
#define LN_EPS 1e-5f

// Scratch (no allocations allowed -> __device__ globals)
__device__ float g_rec_part[NCHUNK][BB][HH];   // 8 MB partial sums (.wb -> L2)
__device__ float g_gemm[BB][HH];               // x @ fc_w^T + h_pre @ weight
__device__ float g_pre[BB][HH];                // gemm + fc_b + sum(partials)
__device__ float g_etah[BB][HH];               // eta * h_post

__device__ __forceinline__ float4 ldcs4(const float4* p)
{
    float4 v;
    asm volatile("ld.global.cs.v4.f32 {%0,%1,%2,%3}, [%4];"
                 : "=f"(v.x), "=f"(v.y), "=f"(v.z), "=f"(v.w) : "l"(p));
    return v;
}

__device__ __forceinline__ void stcs4(float4* p, float4 v)
{
    asm volatile("st.global.cs.v4.f32 [%0], {%1,%2,%3,%4};"
                 :: "l"(p), "f"(v.x), "f"(v.y), "f"(v.z), "f"(v.w));
}

// ---------------------------------------------------------------------------
// Kernel A: rec hebb partials (alpha-only; weight folded into gemm_kernel).
// part[chunk][b][k] = sum_{h in chunk} h_pre[b,h] * alpha[h,k] * hebb[b,h,k]
// R10 theory: rec is LTS-throughput-bound (~7 TB/s total L2 traffic). Cut L2
// bytes: weight gone (-128 MB), BTILE 2->4 halves alpha re-reads (-128 MB):
// LTS = 268 hebb + 64 alpha + 8 part = 340 MB. __launch_bounds__(256,4)
// keeps 32 warps/SM (alpha-only loop ~55 regs, no spill at 64-reg cap).
// Grid = 32 x 16 = 512 blocks.
// ---------------------------------------------------------------------------
__global__ __launch_bounds__(256, 4) void rec_partial_kernel(
    const float* __restrict__ h_pre, const float* __restrict__ hebb,
    const float* __restrict__ alpha)
{
    const int chunk = blockIdx.x;        // 0..NCHUNK-1
    const int bg    = blockIdx.y;        // 0..BGROUPS-1
    const int tid   = threadIdx.x;       // 0..255 -> float4 lane over k
    const int b0    = bg * BTILE;
    const int h0    = chunk * HCHUNK;

    __shared__ float hp[BTILE][HCHUNK];
    if (tid < BTILE * HCHUNK) {
        int j  = tid >> 5;               // 0..3
        int hh = tid & 31;               // 0..31
        hp[j][hh] = h_pre[(b0 + j) * HH + h0 + hh];
    }
    __syncthreads();

    const float4* a4 = reinterpret_cast<const float4*>(alpha);
    const float4* e4 = reinterpret_cast<const float4*>(hebb);

    float4 acc[BTILE];
#pragma unroll
    for (int j = 0; j < BTILE; ++j) acc[j] = make_float4(0.f, 0.f, 0.f, 0.f);

    const float4* pj[BTILE];
#pragma unroll
    for (int j = 0; j < BTILE; ++j)
        pj[j] = e4 + ((b0 + j) * HH + h0) * (HH / 4) + tid;

#pragma unroll 2
    for (int hi = 0; hi < HCHUNK; ++hi) {
        const int h = h0 + hi;
        const float4 a = a4[h * (HH / 4) + tid];
        float4 e[BTILE];
#pragma unroll
        for (int j = 0; j < BTILE; ++j)
            e[j] = ldcs4(pj[j] + hi * (HH / 4));
#pragma unroll
        for (int j = 0; j < BTILE; ++j) {
            const float s = hp[j][hi];
            acc[j].x = fmaf(s * a.x, e[j].x, acc[j].x);
            acc[j].y = fmaf(s * a.y, e[j].y, acc[j].y);
            acc[j].z = fmaf(s * a.z, e[j].z, acc[j].z);
            acc[j].w = fmaf(s * a.w, e[j].w, acc[j].w);
        }
    }

#pragma unroll
    for (int j = 0; j < BTILE; ++j) {
        float4* dst = reinterpret_cast<float4*>(&g_rec_part[chunk][b0 + j][0]);
        dst[tid] = acc[j];   // .wb: keep in L2 for presum
    }
}

// ---------------------------------------------------------------------------
// Kernel B1: g_gemm[b,k] = sum_i x[b,i]*fc_w[k,i] + sum_h h_pre[b,h]*weight[h,k]
// 64 blocks; each block: 64 b x 16 k. Phase 1 over I (fc_w row-major in k),
// phase 2 over H (weight accessed [h][k] -> smem-transposed tile).
// Weight read exactly once (4 MB), ~4 us of extra FMA inside this kernel
// (R6 lesson: as a standalone 16-block kernel this cost ~35 us).
// ---------------------------------------------------------------------------
__global__ __launch_bounds__(256) void gemm_kernel(
    const float* __restrict__ x, const float* __restrict__ fc_w,
    const float* __restrict__ h_pre, const float* __restrict__ weight)
{
    __shared__ float xs[64][33];   // [b][chunk]
    __shared__ float ws[16][33];   // fc_w tile [k][i-chunk]
    __shared__ float wt[32][17];   // weight tile [h-chunk][k]
    const int k0  = blockIdx.x * 16;
    const int tid = threadIdx.x;
    const int tx  = tid & 15;   // k within tile
    const int ty  = tid >> 4;   // b group (4 rows)

    float acc[4] = {0.f, 0.f, 0.f, 0.f};

    // Phase 1: x @ fc_w^T over I
    for (int i0 = 0; i0 < II; i0 += 32) {
        __syncthreads();
#pragma unroll
        for (int r = 0; r < 8; ++r) {
            int idx = tid + r * 256;
            int row = idx >> 5;   // 0..63
            int col = idx & 31;   // 0..31
            xs[row][col] = x[row * II + i0 + col];
        }
        {
            int row = tid >> 5;   // 0..7 -> two passes cover 16 rows
            int col = tid & 31;
            ws[row][col]     = fc_w[(k0 + row) * II + i0 + col];
            ws[row + 8][col] = fc_w[(k0 + row + 8) * II + i0 + col];
        }
        __syncthreads();
#pragma unroll
        for (int ii = 0; ii < 32; ++ii) {
            const float wv = ws[tx][ii];
#pragma unroll
            for (int q = 0; q < 4; ++q)
                acc[q] = fmaf(xs[ty * 4 + q][ii], wv, acc[q]);
        }
    }

    // Phase 2: h_pre @ weight over H (weight rows = reduction dim)
    for (int h0 = 0; h0 < HH; h0 += 32) {
        __syncthreads();
#pragma unroll
        for (int r = 0; r < 8; ++r) {
            int idx = tid + r * 256;
            int row = idx >> 5;   // 0..63 (batch)
            int col = idx & 31;   // 0..31 (h)
            xs[row][col] = h_pre[row * HH + h0 + col];
        }
        {
            int row = tid >> 4;   // 0..15
            int col = tid & 15;   // 0..15
            wt[row][col]      = weight[(h0 + row) * HH + k0 + col];
            wt[row + 16][col] = weight[(h0 + row + 16) * HH + k0 + col];
        }
        __syncthreads();
#pragma unroll
        for (int ii = 0; ii < 32; ++ii) {
            const float wv = wt[ii][tx];
#pragma unroll
            for (int q = 0; q < 4; ++q)
                acc[q] = fmaf(xs[ty * 4 + q][ii], wv, acc[q]);
        }
    }

#pragma unroll
    for (int q = 0; q < 4; ++q)
        g_gemm[ty * 4 + q][k0 + tx] = acc[q];
}

// ---------------------------------------------------------------------------
// Kernel B1b: presum. g_pre[b,k] = g_gemm[b,k] + fc_b[k] + sum_c part[c][b][k]
// Grid (64 b, 8 k-slices) = 512 blocks; partials L2-hot. (R7-measured OK.)
// ---------------------------------------------------------------------------
__global__ __launch_bounds__(256) void presum_kernel(const float* __restrict__ fc_b)
{
    const int b    = blockIdx.x;
    const int sl   = blockIdx.y;          // k-slice: 128 floats = 32 float4
    const int tid  = threadIdx.x;
    const int lane = tid & 31;            // float4 lane within slice
    const int cg   = tid >> 5;            // chunk group 0..7

    const int f4base = sl * 32 + lane;    // float4 index within row

    float4 s = make_float4(0.f, 0.f, 0.f, 0.f);
#pragma unroll
    for (int c = 0; c < 4; ++c) {
        const float4 p = reinterpret_cast<const float4*>(&g_rec_part[cg * 4 + c][b][0])[f4base];
        s.x += p.x; s.y += p.y; s.z += p.z; s.w += p.w;
    }

    __shared__ float4 red[8][32];
    red[cg][lane] = s;
    __syncthreads();

    if (cg == 0) {
        float4 v = red[0][lane];
#pragma unroll
        for (int g = 1; g < 8; ++g) {
            const float4 p = red[g][lane];
            v.x += p.x; v.y += p.y; v.z += p.z; v.w += p.w;
        }
        const float4 gm = reinterpret_cast<const float4*>(&g_gemm[b][0])[f4base];
        const float4 fb = reinterpret_cast<const float4*>(fc_b)[f4base];
        v.x += gm.x + fb.x; v.y += gm.y + fb.y;
        v.z += gm.z + fb.z; v.w += gm.w + fb.w;
        reinterpret_cast<float4*>(&g_pre[b][0])[f4base] = v;
    }
}

// ---------------------------------------------------------------------------
// Kernel B2: per-batch LN + tanh + m + etah (reads only g_pre, L2-hot).
// ---------------------------------------------------------------------------
__device__ __forceinline__ float block_reduce_sum(float v, float* sred, int tid)
{
#pragma unroll
    for (int o = 16; o > 0; o >>= 1) v += __shfl_down_sync(0xffffffffu, v, o);
    if ((tid & 31) == 0) sred[tid >> 5] = v;
    __syncthreads();
    if (tid < 8) {
        float x = sred[tid];
#pragma unroll
        for (int o = 4; o > 0; o >>= 1) x += __shfl_down_sync(0xffu, x, o);
        if (tid == 0) sred[0] = x;
    }
    __syncthreads();
    float r = sred[0];
    __syncthreads();   // protect sred for next reduction
    return r;
}

__global__ __launch_bounds__(256) void ln_mod_kernel(
    const float* __restrict__ ln_g,  const float* __restrict__ ln_b,
    const float* __restrict__ mod_w, const float* __restrict__ mod_b,
    const float* __restrict__ modf_w, const float* __restrict__ modf_b,
    float* __restrict__ out_hpost, float* __restrict__ out_m)
{
    const int b   = blockIdx.x;
    const int tid = threadIdx.x;
    __shared__ float sred[8];
    __shared__ float sm;

    float4 v = reinterpret_cast<const float4*>(&g_pre[b][0])[tid];

    float s  = v.x + v.y + v.z + v.w;
    float s2 = v.x * v.x + v.y * v.y + v.z * v.z + v.w * v.w;
    s  = block_reduce_sum(s,  sred, tid);
    s2 = block_reduce_sum(s2, sred, tid);
    const float mu   = s / (float)HH;
    const float var  = s2 / (float)HH - mu * mu;
    const float rstd = rsqrtf(var + LN_EPS);

    float4 g  = reinterpret_cast<const float4*>(ln_g)[tid];
    float4 be = reinterpret_cast<const float4*>(ln_b)[tid];
    float4 hp;
    hp.x = tanhf((v.x - mu) * rstd * g.x + be.x);
    hp.y = tanhf((v.y - mu) * rstd * g.y + be.y);
    hp.z = tanhf((v.z - mu) * rstd * g.z + be.z);
    hp.w = tanhf((v.w - mu) * rstd * g.w + be.w);
    reinterpret_cast<float4*>(out_hpost + b * HH)[tid] = hp;

    // m = tanh(dot(h_post, mod_w) + mod_b)
    float4 mw = reinterpret_cast<const float4*>(mod_w)[tid];
    float d = hp.x * mw.x + hp.y * mw.y + hp.z * mw.z + hp.w * mw.w;
    d = block_reduce_sum(d, sred, tid);
    if (tid == 0) {
        float m = tanhf(d + mod_b[0]);
        out_m[b] = m;
        sm = m;
    }
    __syncthreads();
    const float m = sm;

    // etah[b,k] = (m*modf_w[k] + modf_b[k]) * h_post[b,k]
    float4 fw  = reinterpret_cast<const float4*>(modf_w)[tid];
    float4 fbb = reinterpret_cast<const float4*>(modf_b)[tid];
    float4 t;
    t.x = fmaf(m, fw.x, fbb.x) * hp.x;
    t.y = fmaf(m, fw.y, fbb.y) * hp.y;
    t.z = fmaf(m, fw.z, fbb.z) * hp.z;
    t.w = fmaf(m, fw.w, fbb.w) * hp.w;
    reinterpret_cast<float4*>(&g_etah[b][0])[tid] = t;
}

// ---------------------------------------------------------------------------
// Kernel C: hebb_new[b,h,k] = clip(hebb[b,h,k] + h_pre[b,h]*etah[b,k])
// Measured at ~76% of HBM spec across rounds (practical ceiling); unchanged.
// ---------------------------------------------------------------------------
__global__ __launch_bounds__(256) void hebb_update_kernel(
    const float* __restrict__ h_pre, const float* __restrict__ hebb,
    float* __restrict__ out_hebb)
{
    const int row0 = blockIdx.x * CROWS;
    const int tid  = threadIdx.x;
#pragma unroll
    for (int r = 0; r < CROWS; ++r) {
        const int bh = row0 + r;
        const int b  = bh >> 10;
        const float hpv = __ldg(&h_pre[bh]);   // h_pre[b*H + h] == h_pre[bh]
        const float4 e = ldcs4(reinterpret_cast<const float4*>(hebb) + bh * (HH / 4) + tid);
        const float4 t = reinterpret_cast<const float4*>(&g_etah[b][0])[tid];
        float4 o;
        o.x = fminf(fmaxf(fmaf(hpv, t.x, e.x), -CLIPV), CLIPV);
        o.y = fminf(fmaxf(fmaf(hpv, t.y, e.y), -CLIPV), CLIPV);
        o.z = fminf(fmaxf(fmaf(hpv, t.z, e.z), -CLIPV), CLIPV);
        o.w = fminf(fmaxf(fmaf(hpv, t.w, e.w), -CLIPV), CLIPV);
        stcs4(reinterpret_cast<float4*>(out_hebb) + bh * (HH / 4) + tid, o);
    }
}

// ---------------------------------------------------------------------------
// Launch. Inputs in metadata order:
// 0 x, 1 h_pre, 2 hebb, 3 fc_w, 4 fc_b, 5 weight, 6 alpha,
// 7 ln_g, 8 ln_b, 9 mod_w, 10 mod_b, 11 modf_w, 12 modf_b
// Output: h_post [64*1024] | m [64] | hebb_new [64*1024*1024], fp32.
// ---------------------------------------------------------------------------
extern "C" void kernel_launch(void* const* d_in, const int* in_sizes, int n_in,
                              void* d_out, int out_size)
{
    const float* x      = (const float*)d_in[0];
    const float* h_pre  = (const float*)d_in[1];
    const float* hebb   = (const float*)d_in[2];
    const float* fc_w   = (const float*)d_in[3];
    const float* fc_b   = (const float*)d_in[4];
    const float* weight = (const float*)d_in[5];
    const float* alpha  = (const float*)d_in[6];
    const float* ln_g   = (const float*)d_in[7];
    const float* ln_b   = (const float*)d_in[8];
    const float* mod_w  = (const float*)d_in[9];
    const float* mod_b  = (const float*)d_in[10];
    const float* modf_w = (const float*)d_in[11];
    const float* modf_b = (const float*)d_in[12];

    float* out       = (float*)d_out;
    float* out_hpost = out;                 // 64*1024
    float* out_m     = out + BB * HH;       // 64
    float* out_hebb  = out + BB * HH + BB;  // 64*1024*1024

    gemm_kernel<<<HH / 16, 256>>>(x, fc_w, h_pre, weight);
    rec_partial_kernel<<<dim3(NCHUNK, BGROUPS), 256>>>(h_pre, hebb, alpha);
    presum_kernel<<<dim3(BB, 8), 256>>>(fc_b);
    ln_mod_kernel<<<BB, 256>>>(ln_g, ln_b, mod_w, mod_b, modf_w, modf_b,
                               out_hpost, out_m);
    hebb_update_kernel<<<(BB * HH) / CROWS, 256>>>(h_pre, hebb, out_hebb);
}

// round 13
// speedup vs baseline: 1.1898x; 1.1898x over previous
#include <cuda_runtime.h>

#define BB 64
#define II 512
#define HH 1024
#define NCHUNK 32              // h-dimension split for rec partials
#define HCHUNK (HH / NCHUNK)   // 32
#define BTILE 4                // batches per block in rec kernel
#define BGROUPS (BB / BTILE)   // 16
#define CROWS 8                // (b,h) rows per block in hebb update
#define WSEG 8                 // K-segments for h_pre@weight
#define XSEG 4                 // K-segments for x@fc_w^T
#define CLIPV 2.0f
#define LN_EPS 1e-5f

// Scratch (no allocations allowed -> __device__ globals)
__device__ float g_rec_part[NCHUNK][BB][HH];     // 8 MB rec partials
__device__ float g_mm_part[WSEG + XSEG][BB][HH]; // 3 MB gemm partials (0..7 w, 8..11 x)
__device__ float g_pre[BB][HH];                  // fc_b + all partials
__device__ float g_etah[BB][HH];                 // eta * h_post

__device__ __forceinline__ float4 ldcs4(const float4* p)
{
    float4 v;
    asm volatile("ld.global.cs.v4.f32 {%0,%1,%2,%3}, [%4];"
                 : "=f"(v.x), "=f"(v.y), "=f"(v.z), "=f"(v.w) : "l"(p));
    return v;
}

__device__ __forceinline__ void stcs4(float4* p, float4 v)
{
    asm volatile("st.global.cs.v4.f32 [%0], {%1,%2,%3,%4};"
                 :: "l"(p), "f"(v.x), "f"(v.y), "f"(v.z), "f"(v.w));
}

// ---------------------------------------------------------------------------
// Kernel A: rec hebb partials (alpha-only; weight handled by wgemm_kernel).
// part[chunk][b][k] = sum_{h in chunk} h_pre[b,h] * alpha[h,k] * hebb[b,h,k]
// LTS theory: rec pinned at ~7 TB/s L2 throughput. Bytes: 268 hebb + 64
// alpha (BTILE=4 re-reads) + 8 partials = 340 MB -> ~48us if LTS-bound.
// lb(256,4) -> 32 warps/SM. Grid = 32 x 16 = 512 blocks.
// ---------------------------------------------------------------------------
__global__ __launch_bounds__(256, 4) void rec_partial_kernel(
    const float* __restrict__ h_pre, const float* __restrict__ hebb,
    const float* __restrict__ alpha)
{
    const int chunk = blockIdx.x;        // 0..NCHUNK-1
    const int bg    = blockIdx.y;        // 0..BGROUPS-1
    const int tid   = threadIdx.x;       // 0..255 -> float4 lane over k
    const int b0    = bg * BTILE;
    const int h0    = chunk * HCHUNK;

    __shared__ float hp[BTILE][HCHUNK];
    if (tid < BTILE * HCHUNK) {
        int j  = tid >> 5;               // 0..3
        int hh = tid & 31;               // 0..31
        hp[j][hh] = h_pre[(b0 + j) * HH + h0 + hh];
    }
    __syncthreads();

    const float4* a4 = reinterpret_cast<const float4*>(alpha);
    const float4* e4 = reinterpret_cast<const float4*>(hebb);

    float4 acc[BTILE];
#pragma unroll
    for (int j = 0; j < BTILE; ++j) acc[j] = make_float4(0.f, 0.f, 0.f, 0.f);

    const float4* pj[BTILE];
#pragma unroll
    for (int j = 0; j < BTILE; ++j)
        pj[j] = e4 + ((b0 + j) * HH + h0) * (HH / 4) + tid;

#pragma unroll 2
    for (int hi = 0; hi < HCHUNK; ++hi) {
        const int h = h0 + hi;
        const float4 a = a4[h * (HH / 4) + tid];
        float4 e[BTILE];
#pragma unroll
        for (int j = 0; j < BTILE; ++j)
            e[j] = ldcs4(pj[j] + hi * (HH / 4));
#pragma unroll
        for (int j = 0; j < BTILE; ++j) {
            const float s = hp[j][hi];
            acc[j].x = fmaf(s * a.x, e[j].x, acc[j].x);
            acc[j].y = fmaf(s * a.y, e[j].y, acc[j].y);
            acc[j].z = fmaf(s * a.z, e[j].z, acc[j].z);
            acc[j].w = fmaf(s * a.w, e[j].w, acc[j].w);
        }
    }

#pragma unroll
    for (int j = 0; j < BTILE; ++j) {
        float4* dst = reinterpret_cast<float4*>(&g_rec_part[chunk][b0 + j][0]);
        dst[tid] = acc[j];   // .wb: keep in L2 for presum
    }
}

// ---------------------------------------------------------------------------
// Kernel W: mm_part[seg] = h_pre[:, seg*128:(seg+1)*128] @ weight[seg rows]
// Register-tiled GEMM: block = 64b x 64k x 128h, 4x4 out/thread
// (0.5 LDS/FMA vs 1.25 in the old design). Grid 16 k-tiles x 8 segs = 128.
// ---------------------------------------------------------------------------
__global__ __launch_bounds__(256) void wgemm_kernel(
    const float* __restrict__ h_pre, const float* __restrict__ weight)
{
    __shared__ float hsm[64][33];   // [b][h-step]
    __shared__ float wsm[32][65];   // [h-step][k]
    const int k0  = blockIdx.x * 64;
    const int seg = blockIdx.y;
    const int tid = threadIdx.x;
    const int tx  = tid & 15;       // k quad
    const int ty  = tid >> 4;       // b quad

    float acc[4][4];
#pragma unroll
    for (int i = 0; i < 4; ++i)
#pragma unroll
        for (int j = 0; j < 4; ++j) acc[i][j] = 0.f;

    for (int step = 0; step < 4; ++step) {
        const int hh0 = seg * 128 + step * 32;
        __syncthreads();
#pragma unroll
        for (int r = 0; r < 8; ++r) {
            int idx = tid + r * 256;
            int row = idx >> 5;     // 0..63 (b)
            int col = idx & 31;     // 0..31 (h)
            hsm[row][col] = h_pre[row * HH + hh0 + col];
        }
#pragma unroll
        for (int r = 0; r < 8; ++r) {
            int idx = tid + r * 256;
            int row = idx >> 6;     // 0..31 (h)
            int col = idx & 63;     // 0..63 (k)
            wsm[row][col] = weight[(hh0 + row) * HH + k0 + col];
        }
        __syncthreads();
#pragma unroll
        for (int ii = 0; ii < 32; ++ii) {
            float xv[4], wv[4];
#pragma unroll
            for (int q = 0; q < 4; ++q) { xv[q] = hsm[ty * 4 + q][ii]; wv[q] = wsm[ii][tx * 4 + q]; }
#pragma unroll
            for (int bi = 0; bi < 4; ++bi)
#pragma unroll
                for (int ki = 0; ki < 4; ++ki)
                    acc[bi][ki] = fmaf(xv[bi], wv[ki], acc[bi][ki]);
        }
    }

#pragma unroll
    for (int bi = 0; bi < 4; ++bi)
#pragma unroll
        for (int ki = 0; ki < 4; ++ki)
            g_mm_part[seg][ty * 4 + bi][k0 + tx * 4 + ki] = acc[bi][ki];
}

// ---------------------------------------------------------------------------
// Kernel X: mm_part[WSEG+seg] = x[:, seg*128:+128] @ fc_w[:, same]^T
// Same register-tiled structure; fc_w is [k][i] so its tile loads directly
// as [k][i-step] (no transpose). Grid 16 k-tiles x 4 segs = 64 blocks.
// ---------------------------------------------------------------------------
__global__ __launch_bounds__(256) void xgemm_kernel(
    const float* __restrict__ x, const float* __restrict__ fc_w)
{
    __shared__ float xsm[64][33];   // [b][i-step]
    __shared__ float wsm[64][33];   // [k][i-step]
    const int k0  = blockIdx.x * 64;
    const int seg = blockIdx.y;
    const int tid = threadIdx.x;
    const int tx  = tid & 15;       // k quad
    const int ty  = tid >> 4;       // b quad

    float acc[4][4];
#pragma unroll
    for (int i = 0; i < 4; ++i)
#pragma unroll
        for (int j = 0; j < 4; ++j) acc[i][j] = 0.f;

    for (int step = 0; step < 4; ++step) {
        const int ii0 = seg * 128 + step * 32;
        __syncthreads();
#pragma unroll
        for (int r = 0; r < 8; ++r) {
            int idx = tid + r * 256;
            int row = idx >> 5;     // 0..63
            int col = idx & 31;     // 0..31
            xsm[row][col] = x[row * II + ii0 + col];
            wsm[row][col] = fc_w[(k0 + row) * II + ii0 + col];
        }
        __syncthreads();
#pragma unroll
        for (int ii = 0; ii < 32; ++ii) {
            float xv[4], wv[4];
#pragma unroll
            for (int q = 0; q < 4; ++q) { xv[q] = xsm[ty * 4 + q][ii]; wv[q] = wsm[tx * 4 + q][ii]; }
#pragma unroll
            for (int bi = 0; bi < 4; ++bi)
#pragma unroll
                for (int ki = 0; ki < 4; ++ki)
                    acc[bi][ki] = fmaf(xv[bi], wv[ki], acc[bi][ki]);
        }
    }

#pragma unroll
    for (int bi = 0; bi < 4; ++bi)
#pragma unroll
        for (int ki = 0; ki < 4; ++ki)
            g_mm_part[WSEG + seg][ty * 4 + bi][k0 + tx * 4 + ki] = acc[bi][ki];
}

// ---------------------------------------------------------------------------
// Kernel P: presum. g_pre[b,k] = fc_b[k] + sum_c rec_part[c] + sum_s mm_part[s]
// Grid (64 b, 8 k-slices) = 512 blocks. cg 0..7 sums 4 rec planes + mm plane
// cg; cg 0..3 also sums mm plane 8+cg. All planes L2-hot.
// ---------------------------------------------------------------------------
__global__ __launch_bounds__(256) void presum_kernel(const float* __restrict__ fc_b)
{
    const int b    = blockIdx.x;
    const int sl   = blockIdx.y;          // k-slice: 128 floats = 32 float4
    const int tid  = threadIdx.x;
    const int lane = tid & 31;            // float4 lane within slice
    const int cg   = tid >> 5;            // chunk group 0..7

    const int f4base = sl * 32 + lane;    // float4 index within row

    float4 s = make_float4(0.f, 0.f, 0.f, 0.f);
#pragma unroll
    for (int c = 0; c < 4; ++c) {
        const float4 p = reinterpret_cast<const float4*>(&g_rec_part[cg * 4 + c][b][0])[f4base];
        s.x += p.x; s.y += p.y; s.z += p.z; s.w += p.w;
    }
    {
        const float4 p = reinterpret_cast<const float4*>(&g_mm_part[cg][b][0])[f4base];
        s.x += p.x; s.y += p.y; s.z += p.z; s.w += p.w;
    }
    if (cg < XSEG) {
        const float4 p = reinterpret_cast<const float4*>(&g_mm_part[WSEG + cg][b][0])[f4base];
        s.x += p.x; s.y += p.y; s.z += p.z; s.w += p.w;
    }

    __shared__ float4 red[8][32];
    red[cg][lane] = s;
    __syncthreads();

    if (cg == 0) {
        float4 v = red[0][lane];
#pragma unroll
        for (int g = 1; g < 8; ++g) {
            const float4 p = red[g][lane];
            v.x += p.x; v.y += p.y; v.z += p.z; v.w += p.w;
        }
        const float4 fb = reinterpret_cast<const float4*>(fc_b)[f4base];
        v.x += fb.x; v.y += fb.y; v.z += fb.z; v.w += fb.w;
        reinterpret_cast<float4*>(&g_pre[b][0])[f4base] = v;
    }
}

// ---------------------------------------------------------------------------
// Kernel B2: per-batch LN + tanh + m + etah (reads only g_pre, L2-hot).
// ---------------------------------------------------------------------------
__device__ __forceinline__ float block_reduce_sum(float v, float* sred, int tid)
{
#pragma unroll
    for (int o = 16; o > 0; o >>= 1) v += __shfl_down_sync(0xffffffffu, v, o);
    if ((tid & 31) == 0) sred[tid >> 5] = v;
    __syncthreads();
    if (tid < 8) {
        float x = sred[tid];
#pragma unroll
        for (int o = 4; o > 0; o >>= 1) x += __shfl_down_sync(0xffu, x, o);
        if (tid == 0) sred[0] = x;
    }
    __syncthreads();
    float r = sred[0];
    __syncthreads();   // protect sred for next reduction
    return r;
}

__global__ __launch_bounds__(256) void ln_mod_kernel(
    const float* __restrict__ ln_g,  const float* __restrict__ ln_b,
    const float* __restrict__ mod_w, const float* __restrict__ mod_b,
    const float* __restrict__ modf_w, const float* __restrict__ modf_b,
    float* __restrict__ out_hpost, float* __restrict__ out_m)
{
    const int b   = blockIdx.x;
    const int tid = threadIdx.x;
    __shared__ float sred[8];
    __shared__ float sm;

    float4 v = reinterpret_cast<const float4*>(&g_pre[b][0])[tid];

    float s  = v.x + v.y + v.z + v.w;
    float s2 = v.x * v.x + v.y * v.y + v.z * v.z + v.w * v.w;
    s  = block_reduce_sum(s,  sred, tid);
    s2 = block_reduce_sum(s2, sred, tid);
    const float mu   = s / (float)HH;
    const float var  = s2 / (float)HH - mu * mu;
    const float rstd = rsqrtf(var + LN_EPS);

    float4 g  = reinterpret_cast<const float4*>(ln_g)[tid];
    float4 be = reinterpret_cast<const float4*>(ln_b)[tid];
    float4 hp;
    hp.x = tanhf((v.x - mu) * rstd * g.x + be.x);
    hp.y = tanhf((v.y - mu) * rstd * g.y + be.y);
    hp.z = tanhf((v.z - mu) * rstd * g.z + be.z);
    hp.w = tanhf((v.w - mu) * rstd * g.w + be.w);
    reinterpret_cast<float4*>(out_hpost + b * HH)[tid] = hp;

    // m = tanh(dot(h_post, mod_w) + mod_b)
    float4 mw = reinterpret_cast<const float4*>(mod_w)[tid];
    float d = hp.x * mw.x + hp.y * mw.y + hp.z * mw.z + hp.w * mw.w;
    d = block_reduce_sum(d, sred, tid);
    if (tid == 0) {
        float m = tanhf(d + mod_b[0]);
        out_m[b] = m;
        sm = m;
    }
    __syncthreads();
    const float m = sm;

    // etah[b,k] = (m*modf_w[k] + modf_b[k]) * h_post[b,k]
    float4 fw  = reinterpret_cast<const float4*>(modf_w)[tid];
    float4 fbb = reinterpret_cast<const float4*>(modf_b)[tid];
    float4 t;
    t.x = fmaf(m, fw.x, fbb.x) * hp.x;
    t.y = fmaf(m, fw.y, fbb.y) * hp.y;
    t.z = fmaf(m, fw.z, fbb.z) * hp.z;
    t.w = fmaf(m, fw.w, fbb.w) * hp.w;
    reinterpret_cast<float4*>(&g_etah[b][0])[tid] = t;
}

// ---------------------------------------------------------------------------
// Kernel C: hebb_new[b,h,k] = clip(hebb[b,h,k] + h_pre[b,h]*etah[b,k])
// Measured at ~76% of HBM spec across rounds (practical ceiling); unchanged.
// ---------------------------------------------------------------------------
__global__ __launch_bounds__(256) void hebb_update_kernel(
    const float* __restrict__ h_pre, const float* __restrict__ hebb,
    float* __restrict__ out_hebb)
{
    const int row0 = blockIdx.x * CROWS;
    const int tid  = threadIdx.x;
#pragma unroll
    for (int r = 0; r < CROWS; ++r) {
        const int bh = row0 + r;
        const int b  = bh >> 10;
        const float hpv = __ldg(&h_pre[bh]);   // h_pre[b*H + h] == h_pre[bh]
        const float4 e = ldcs4(reinterpret_cast<const float4*>(hebb) + bh * (HH / 4) + tid);
        const float4 t = reinterpret_cast<const float4*>(&g_etah[b][0])[tid];
        float4 o;
        o.x = fminf(fmaxf(fmaf(hpv, t.x, e.x), -CLIPV), CLIPV);
        o.y = fminf(fmaxf(fmaf(hpv, t.y, e.y), -CLIPV), CLIPV);
        o.z = fminf(fmaxf(fmaf(hpv, t.z, e.z), -CLIPV), CLIPV);
        o.w = fminf(fmaxf(fmaf(hpv, t.w, e.w), -CLIPV), CLIPV);
        stcs4(reinterpret_cast<float4*>(out_hebb) + bh * (HH / 4) + tid, o);
    }
}

// ---------------------------------------------------------------------------
// Launch. Inputs in metadata order:
// 0 x, 1 h_pre, 2 hebb, 3 fc_w, 4 fc_b, 5 weight, 6 alpha,
// 7 ln_g, 8 ln_b, 9 mod_w, 10 mod_b, 11 modf_w, 12 modf_b
// Output: h_post [64*1024] | m [64] | hebb_new [64*1024*1024], fp32.
// ---------------------------------------------------------------------------
extern "C" void kernel_launch(void* const* d_in, const int* in_sizes, int n_in,
                              void* d_out, int out_size)
{
    const float* x      = (const float*)d_in[0];
    const float* h_pre  = (const float*)d_in[1];
    const float* hebb   = (const float*)d_in[2];
    const float* fc_w   = (const float*)d_in[3];
    const float* fc_b   = (const float*)d_in[4];
    const float* weight = (const float*)d_in[5];
    const float* alpha  = (const float*)d_in[6];
    const float* ln_g   = (const float*)d_in[7];
    const float* ln_b   = (const float*)d_in[8];
    const float* mod_w  = (const float*)d_in[9];
    const float* mod_b  = (const float*)d_in[10];
    const float* modf_w = (const float*)d_in[11];
    const float* modf_b = (const float*)d_in[12];

    float* out       = (float*)d_out;
    float* out_hpost = out;                 // 64*1024
    float* out_m     = out + BB * HH;       // 64
    float* out_hebb  = out + BB * HH + BB;  // 64*1024*1024

    rec_partial_kernel<<<dim3(NCHUNK, BGROUPS), 256>>>(h_pre, hebb, alpha);
    wgemm_kernel<<<dim3(HH / 64, WSEG), 256>>>(h_pre, weight);
    xgemm_kernel<<<dim3(HH / 64, XSEG), 256>>>(x, fc_w);
    presum_kernel<<<dim3(BB, 8), 256>>>(fc_b);
    ln_mod_kernel<<<BB, 256>>>(ln_g, ln_b, mod_w, mod_b, modf_w, modf_b,
                               out_hpost, out_m);
    hebb_update_kernel<<<(BB * HH) / CROWS, 256>>>(h_pre, hebb, out_hebb);
}

// round 14
// speedup vs baseline: 1.2207x; 1.0260x over previous
#include <cuda_runtime.h>

#define BB 64
#define II 512
#define HH 1024
#define NCHUNK 32              // h-dimension split for rec partials
#define HCHUNK (HH / NCHUNK)   // 32
#define BTILE 4                // batches per block in rec kernel
#define BGROUPS (BB / BTILE)   // 16
#define CROWS 8                // (b,h) rows per block in hebb update
#define WSEG 8                 // K-segments for h_pre@weight
#define XSEG 4                 // K-segments for x@fc_w^T
#define CLIPV 2.0f
#define LN_EPS 1e-5f

// Scratch (no allocations allowed -> __device__ globals)
__device__ float g_pre[BB][HH];    // fc_b + all contributions (atomic accum)
__device__ float g_etah[BB][HH];   // eta * h_post

__device__ __forceinline__ float4 ldcs4(const float4* p)
{
    float4 v;
    asm volatile("ld.global.cs.v4.f32 {%0,%1,%2,%3}, [%4];"
                 : "=f"(v.x), "=f"(v.y), "=f"(v.z), "=f"(v.w) : "l"(p));
    return v;
}

__device__ __forceinline__ void stcs4(float4* p, float4 v)
{
    asm volatile("st.global.cs.v4.f32 [%0], {%1,%2,%3,%4};"
                 :: "l"(p), "f"(v.x), "f"(v.y), "f"(v.z), "f"(v.w));
}

// ---------------------------------------------------------------------------
// Kernel 0: g_pre[b][k] = fc_b[k]  (base for atomic accumulation)
// ---------------------------------------------------------------------------
__global__ __launch_bounds__(256) void init_pre_kernel(const float* __restrict__ fc_b)
{
    const int b   = blockIdx.x;
    const int tid = threadIdx.x;
    reinterpret_cast<float4*>(&g_pre[b][0])[tid] =
        reinterpret_cast<const float4*>(fc_b)[tid];
}

// ---------------------------------------------------------------------------
// Kernel A: rec hebb contribution, atomically accumulated into g_pre.
// g_pre[b][k] += sum_{h in chunk} h_pre[b,h] * alpha[h,k] * hebb[b,h,k]
// LTS bytes: 268 hebb + 64 alpha re-reads + 8 atomic = 340 MB.
// lb(256,4) -> 32 warps/SM. Grid = 32 x 16 = 512 blocks.
// ---------------------------------------------------------------------------
__global__ __launch_bounds__(256, 4) void rec_partial_kernel(
    const float* __restrict__ h_pre, const float* __restrict__ hebb,
    const float* __restrict__ alpha)
{
    const int chunk = blockIdx.x;        // 0..NCHUNK-1
    const int bg    = blockIdx.y;        // 0..BGROUPS-1
    const int tid   = threadIdx.x;       // 0..255 -> float4 lane over k
    const int b0    = bg * BTILE;
    const int h0    = chunk * HCHUNK;

    __shared__ float hp[BTILE][HCHUNK];
    if (tid < BTILE * HCHUNK) {
        int j  = tid >> 5;               // 0..3
        int hh = tid & 31;               // 0..31
        hp[j][hh] = h_pre[(b0 + j) * HH + h0 + hh];
    }
    __syncthreads();

    const float4* a4 = reinterpret_cast<const float4*>(alpha);
    const float4* e4 = reinterpret_cast<const float4*>(hebb);

    float4 acc[BTILE];
#pragma unroll
    for (int j = 0; j < BTILE; ++j) acc[j] = make_float4(0.f, 0.f, 0.f, 0.f);

    const float4* pj[BTILE];
#pragma unroll
    for (int j = 0; j < BTILE; ++j)
        pj[j] = e4 + ((b0 + j) * HH + h0) * (HH / 4) + tid;

#pragma unroll 2
    for (int hi = 0; hi < HCHUNK; ++hi) {
        const int h = h0 + hi;
        const float4 a = a4[h * (HH / 4) + tid];
        float4 e[BTILE];
#pragma unroll
        for (int j = 0; j < BTILE; ++j)
            e[j] = ldcs4(pj[j] + hi * (HH / 4));
#pragma unroll
        for (int j = 0; j < BTILE; ++j) {
            const float s = hp[j][hi];
            acc[j].x = fmaf(s * a.x, e[j].x, acc[j].x);
            acc[j].y = fmaf(s * a.y, e[j].y, acc[j].y);
            acc[j].z = fmaf(s * a.z, e[j].z, acc[j].z);
            acc[j].w = fmaf(s * a.w, e[j].w, acc[j].w);
        }
    }

#pragma unroll
    for (int j = 0; j < BTILE; ++j)
        atomicAdd(reinterpret_cast<float4*>(&g_pre[b0 + j][0]) + tid, acc[j]);
}

// ---------------------------------------------------------------------------
// Kernel W: g_pre += h_pre[:, seg*128:+128] @ weight[seg rows]
// Register-tiled GEMM: block = 64b x 64k x 128h, 4x4 out/thread.
// Grid 16 k-tiles x 8 segs = 128 blocks; atomic float4 epilogue.
// ---------------------------------------------------------------------------
__global__ __launch_bounds__(256) void wgemm_kernel(
    const float* __restrict__ h_pre, const float* __restrict__ weight)
{
    __shared__ float hsm[64][33];   // [b][h-step]
    __shared__ float wsm[32][65];   // [h-step][k]
    const int k0  = blockIdx.x * 64;
    const int seg = blockIdx.y;
    const int tid = threadIdx.x;
    const int tx  = tid & 15;       // k quad
    const int ty  = tid >> 4;       // b quad

    float acc[4][4];
#pragma unroll
    for (int i = 0; i < 4; ++i)
#pragma unroll
        for (int j = 0; j < 4; ++j) acc[i][j] = 0.f;

    for (int step = 0; step < 4; ++step) {
        const int hh0 = seg * 128 + step * 32;
        __syncthreads();
#pragma unroll
        for (int r = 0; r < 8; ++r) {
            int idx = tid + r * 256;
            int row = idx >> 5;     // 0..63 (b)
            int col = idx & 31;     // 0..31 (h)
            hsm[row][col] = h_pre[row * HH + hh0 + col];
        }
#pragma unroll
        for (int r = 0; r < 8; ++r) {
            int idx = tid + r * 256;
            int row = idx >> 6;     // 0..31 (h)
            int col = idx & 63;     // 0..63 (k)
            wsm[row][col] = weight[(hh0 + row) * HH + k0 + col];
        }
        __syncthreads();
#pragma unroll
        for (int ii = 0; ii < 32; ++ii) {
            float xv[4], wv[4];
#pragma unroll
            for (int q = 0; q < 4; ++q) { xv[q] = hsm[ty * 4 + q][ii]; wv[q] = wsm[ii][tx * 4 + q]; }
#pragma unroll
            for (int bi = 0; bi < 4; ++bi)
#pragma unroll
                for (int ki = 0; ki < 4; ++ki)
                    acc[bi][ki] = fmaf(xv[bi], wv[ki], acc[bi][ki]);
        }
    }

#pragma unroll
    for (int bi = 0; bi < 4; ++bi) {
        float4 v = make_float4(acc[bi][0], acc[bi][1], acc[bi][2], acc[bi][3]);
        atomicAdd(reinterpret_cast<float4*>(&g_pre[ty * 4 + bi][k0 + tx * 4]), v);
    }
}

// ---------------------------------------------------------------------------
// Kernel X: g_pre += x[:, seg*128:+128] @ fc_w[:, same]^T
// Same structure; fc_w tile loads directly [k][i-step]. Grid 16 x 4 = 64.
// ---------------------------------------------------------------------------
__global__ __launch_bounds__(256) void xgemm_kernel(
    const float* __restrict__ x, const float* __restrict__ fc_w)
{
    __shared__ float xsm[64][33];   // [b][i-step]
    __shared__ float wsm[64][33];   // [k][i-step]
    const int k0  = blockIdx.x * 64;
    const int seg = blockIdx.y;
    const int tid = threadIdx.x;
    const int tx  = tid & 15;       // k quad
    const int ty  = tid >> 4;       // b quad

    float acc[4][4];
#pragma unroll
    for (int i = 0; i < 4; ++i)
#pragma unroll
        for (int j = 0; j < 4; ++j) acc[i][j] = 0.f;

    for (int step = 0; step < 4; ++step) {
        const int ii0 = seg * 128 + step * 32;
        __syncthreads();
#pragma unroll
        for (int r = 0; r < 8; ++r) {
            int idx = tid + r * 256;
            int row = idx >> 5;     // 0..63
            int col = idx & 31;     // 0..31
            xsm[row][col] = x[row * II + ii0 + col];
            wsm[row][col] = fc_w[(k0 + row) * II + ii0 + col];
        }
        __syncthreads();
#pragma unroll
        for (int ii = 0; ii < 32; ++ii) {
            float xv[4], wv[4];
#pragma unroll
            for (int q = 0; q < 4; ++q) { xv[q] = xsm[ty * 4 + q][ii]; wv[q] = wsm[tx * 4 + q][ii]; }
#pragma unroll
            for (int bi = 0; bi < 4; ++bi)
#pragma unroll
                for (int ki = 0; ki < 4; ++ki)
                    acc[bi][ki] = fmaf(xv[bi], wv[ki], acc[bi][ki]);
        }
    }

#pragma unroll
    for (int bi = 0; bi < 4; ++bi) {
        float4 v = make_float4(acc[bi][0], acc[bi][1], acc[bi][2], acc[bi][3]);
        atomicAdd(reinterpret_cast<float4*>(&g_pre[ty * 4 + bi][k0 + tx * 4]), v);
    }
}

// ---------------------------------------------------------------------------
// Kernel B2: per-batch LN + tanh + m + etah (reads only g_pre, L2-hot).
// ---------------------------------------------------------------------------
__device__ __forceinline__ float block_reduce_sum(float v, float* sred, int tid)
{
#pragma unroll
    for (int o = 16; o > 0; o >>= 1) v += __shfl_down_sync(0xffffffffu, v, o);
    if ((tid & 31) == 0) sred[tid >> 5] = v;
    __syncthreads();
    if (tid < 8) {
        float x = sred[tid];
#pragma unroll
        for (int o = 4; o > 0; o >>= 1) x += __shfl_down_sync(0xffu, x, o);
        if (tid == 0) sred[0] = x;
    }
    __syncthreads();
    float r = sred[0];
    __syncthreads();   // protect sred for next reduction
    return r;
}

__global__ __launch_bounds__(256) void ln_mod_kernel(
    const float* __restrict__ ln_g,  const float* __restrict__ ln_b,
    const float* __restrict__ mod_w, const float* __restrict__ mod_b,
    const float* __restrict__ modf_w, const float* __restrict__ modf_b,
    float* __restrict__ out_hpost, float* __restrict__ out_m)
{
    const int b   = blockIdx.x;
    const int tid = threadIdx.x;
    __shared__ float sred[8];
    __shared__ float sm;

    float4 v = reinterpret_cast<const float4*>(&g_pre[b][0])[tid];

    float s  = v.x + v.y + v.z + v.w;
    float s2 = v.x * v.x + v.y * v.y + v.z * v.z + v.w * v.w;
    s  = block_reduce_sum(s,  sred, tid);
    s2 = block_reduce_sum(s2, sred, tid);
    const float mu   = s / (float)HH;
    const float var  = s2 / (float)HH - mu * mu;
    const float rstd = rsqrtf(var + LN_EPS);

    float4 g  = reinterpret_cast<const float4*>(ln_g)[tid];
    float4 be = reinterpret_cast<const float4*>(ln_b)[tid];
    float4 hp;
    hp.x = tanhf((v.x - mu) * rstd * g.x + be.x);
    hp.y = tanhf((v.y - mu) * rstd * g.y + be.y);
    hp.z = tanhf((v.z - mu) * rstd * g.z + be.z);
    hp.w = tanhf((v.w - mu) * rstd * g.w + be.w);
    reinterpret_cast<float4*>(out_hpost + b * HH)[tid] = hp;

    // m = tanh(dot(h_post, mod_w) + mod_b)
    float4 mw = reinterpret_cast<const float4*>(mod_w)[tid];
    float d = hp.x * mw.x + hp.y * mw.y + hp.z * mw.z + hp.w * mw.w;
    d = block_reduce_sum(d, sred, tid);
    if (tid == 0) {
        float m = tanhf(d + mod_b[0]);
        out_m[b] = m;
        sm = m;
    }
    __syncthreads();
    const float m = sm;

    // etah[b,k] = (m*modf_w[k] + modf_b[k]) * h_post[b,k]
    float4 fw  = reinterpret_cast<const float4*>(modf_w)[tid];
    float4 fbb = reinterpret_cast<const float4*>(modf_b)[tid];
    float4 t;
    t.x = fmaf(m, fw.x, fbb.x) * hp.x;
    t.y = fmaf(m, fw.y, fbb.y) * hp.y;
    t.z = fmaf(m, fw.z, fbb.z) * hp.z;
    t.w = fmaf(m, fw.w, fbb.w) * hp.w;
    reinterpret_cast<float4*>(&g_etah[b][0])[tid] = t;
}

// ---------------------------------------------------------------------------
// Kernel C: hebb_new[b,h,k] = clip(hebb[b,h,k] + h_pre[b,h]*etah[b,k])
// Measured at ~76% of HBM spec across rounds (practical ceiling); unchanged.
// ---------------------------------------------------------------------------
__global__ __launch_bounds__(256) void hebb_update_kernel(
    const float* __restrict__ h_pre, const float* __restrict__ hebb,
    float* __restrict__ out_hebb)
{
    const int row0 = blockIdx.x * CROWS;
    const int tid  = threadIdx.x;
#pragma unroll
    for (int r = 0; r < CROWS; ++r) {
        const int bh = row0 + r;
        const int b  = bh >> 10;
        const float hpv = __ldg(&h_pre[bh]);   // h_pre[b*H + h] == h_pre[bh]
        const float4 e = ldcs4(reinterpret_cast<const float4*>(hebb) + bh * (HH / 4) + tid);
        const float4 t = reinterpret_cast<const float4*>(&g_etah[b][0])[tid];
        float4 o;
        o.x = fminf(fmaxf(fmaf(hpv, t.x, e.x), -CLIPV), CLIPV);
        o.y = fminf(fmaxf(fmaf(hpv, t.y, e.y), -CLIPV), CLIPV);
        o.z = fminf(fmaxf(fmaf(hpv, t.z, e.z), -CLIPV), CLIPV);
        o.w = fminf(fmaxf(fmaf(hpv, t.w, e.w), -CLIPV), CLIPV);
        stcs4(reinterpret_cast<float4*>(out_hebb) + bh * (HH / 4) + tid, o);
    }
}

// ---------------------------------------------------------------------------
// Launch. Inputs in metadata order:
// 0 x, 1 h_pre, 2 hebb, 3 fc_w, 4 fc_b, 5 weight, 6 alpha,
// 7 ln_g, 8 ln_b, 9 mod_w, 10 mod_b, 11 modf_w, 12 modf_b
// Output: h_post [64*1024] | m [64] | hebb_new [64*1024*1024], fp32.
// ---------------------------------------------------------------------------
extern "C" void kernel_launch(void* const* d_in, const int* in_sizes, int n_in,
                              void* d_out, int out_size)
{
    const float* x      = (const float*)d_in[0];
    const float* h_pre  = (const float*)d_in[1];
    const float* hebb   = (const float*)d_in[2];
    const float* fc_w   = (const float*)d_in[3];
    const float* fc_b   = (const float*)d_in[4];
    const float* weight = (const float*)d_in[5];
    const float* alpha  = (const float*)d_in[6];
    const float* ln_g   = (const float*)d_in[7];
    const float* ln_b   = (const float*)d_in[8];
    const float* mod_w  = (const float*)d_in[9];
    const float* mod_b  = (const float*)d_in[10];
    const float* modf_w = (const float*)d_in[11];
    const float* modf_b = (const float*)d_in[12];

    float* out       = (float*)d_out;
    float* out_hpost = out;                 // 64*1024
    float* out_m     = out + BB * HH;       // 64
    float* out_hebb  = out + BB * HH + BB;  // 64*1024*1024

    init_pre_kernel<<<BB, 256>>>(fc_b);
    rec_partial_kernel<<<dim3(NCHUNK, BGROUPS), 256>>>(h_pre, hebb, alpha);
    wgemm_kernel<<<dim3(HH / 64, WSEG), 256>>>(h_pre, weight);
    xgemm_kernel<<<dim3(HH / 64, XSEG), 256>>>(x, fc_w);
    ln_mod_kernel<<<BB, 256>>>(ln_g, ln_b, mod_w, mod_b, modf_w, modf_b,
                               out_hpost, out_m);
    hebb_update_kernel<<<(BB * HH) / CROWS, 256>>>(h_pre, hebb, out_hebb);
}

// round 15
// speedup vs baseline: 1.2702x; 1.0405x over previous
#include <cuda_runtime.h>

#define BB 64
#define II 512
#define HH 1024
#define NCHUNK 32              // h-dimension split for rec partials
#define HCHUNK (HH / NCHUNK)   // 32
#define BTILE 4                // batches per block in rec kernel
#define BGROUPS (BB / BTILE)   // 16
#define CROWS 8                // (b,h) rows per block in hebb update
#define WSEG 8                 // K-segments for h_pre@weight
#define XSEG 4                 // K-segments for x@fc_w^T
#define CLIPV 2.0f
#define LN_EPS 1e-5f

// Scratch (no allocations allowed -> __device__ globals)
// g_pre invariant: ZERO at kernel_launch entry. Zero-initialized at module
// load; ln_mod_kernel re-zeroes it after reading, restoring the invariant
// for the next graph replay.
__device__ float g_pre[BB][HH];    // atomic accumulator (rec + both gemms)
__device__ float g_etah[BB][HH];   // eta * h_post

__device__ __forceinline__ float4 ldcs4(const float4* p)
{
    float4 v;
    asm volatile("ld.global.cs.v4.f32 {%0,%1,%2,%3}, [%4];"
                 : "=f"(v.x), "=f"(v.y), "=f"(v.z), "=f"(v.w) : "l"(p));
    return v;
}

__device__ __forceinline__ void stcs4(float4* p, float4 v)
{
    asm volatile("st.global.cs.v4.f32 [%0], {%1,%2,%3,%4};"
                 :: "l"(p), "f"(v.x), "f"(v.y), "f"(v.z), "f"(v.w));
}

// ---------------------------------------------------------------------------
// Kernel A: rec hebb contribution, atomically accumulated into g_pre.
// g_pre[b][k] += sum_{h in chunk} h_pre[b,h] * alpha[h,k] * hebb[b,h,k]
// LTS bytes: 268 hebb + 64 alpha re-reads + 8 atomic = 340 MB.
// lb(256,4) -> 32 warps/SM. Grid = 32 x 16 = 512 blocks. (R13/R14 measured.)
// ---------------------------------------------------------------------------
__global__ __launch_bounds__(256, 4) void rec_partial_kernel(
    const float* __restrict__ h_pre, const float* __restrict__ hebb,
    const float* __restrict__ alpha)
{
    const int chunk = blockIdx.x;        // 0..NCHUNK-1
    const int bg    = blockIdx.y;        // 0..BGROUPS-1
    const int tid   = threadIdx.x;       // 0..255 -> float4 lane over k
    const int b0    = bg * BTILE;
    const int h0    = chunk * HCHUNK;

    __shared__ float hp[BTILE][HCHUNK];
    if (tid < BTILE * HCHUNK) {
        int j  = tid >> 5;               // 0..3
        int hh = tid & 31;               // 0..31
        hp[j][hh] = h_pre[(b0 + j) * HH + h0 + hh];
    }
    __syncthreads();

    const float4* a4 = reinterpret_cast<const float4*>(alpha);
    const float4* e4 = reinterpret_cast<const float4*>(hebb);

    float4 acc[BTILE];
#pragma unroll
    for (int j = 0; j < BTILE; ++j) acc[j] = make_float4(0.f, 0.f, 0.f, 0.f);

    const float4* pj[BTILE];
#pragma unroll
    for (int j = 0; j < BTILE; ++j)
        pj[j] = e4 + ((b0 + j) * HH + h0) * (HH / 4) + tid;

#pragma unroll 2
    for (int hi = 0; hi < HCHUNK; ++hi) {
        const int h = h0 + hi;
        const float4 a = a4[h * (HH / 4) + tid];
        float4 e[BTILE];
#pragma unroll
        for (int j = 0; j < BTILE; ++j)
            e[j] = ldcs4(pj[j] + hi * (HH / 4));
#pragma unroll
        for (int j = 0; j < BTILE; ++j) {
            const float s = hp[j][hi];
            acc[j].x = fmaf(s * a.x, e[j].x, acc[j].x);
            acc[j].y = fmaf(s * a.y, e[j].y, acc[j].y);
            acc[j].z = fmaf(s * a.z, e[j].z, acc[j].z);
            acc[j].w = fmaf(s * a.w, e[j].w, acc[j].w);
        }
    }

#pragma unroll
    for (int j = 0; j < BTILE; ++j)
        atomicAdd(reinterpret_cast<float4*>(&g_pre[b0 + j][0]) + tid, acc[j]);
}

// ---------------------------------------------------------------------------
// Kernel G: BOTH small GEMMs in one launch (overlapped latency).
// blockIdx.y = seg: 0..WSEG-1   -> g_pre += h_pre[:, seg*128:+128] @ weight
//              WSEG..WSEG+XSEG-1 -> g_pre += x[:, s*128:+128] @ fc_w^T
// Register-tiled 64b x 64k, 4x4 out/thread, atomic float4 epilogue.
// Grid 16 x 12 = 192 blocks, single wave (R14: two serial launches = ~17us;
// one wave = ~max per-block latency ~7us).
// ---------------------------------------------------------------------------
__global__ __launch_bounds__(256) void gemm_all_kernel(
    const float* __restrict__ h_pre, const float* __restrict__ weight,
    const float* __restrict__ x, const float* __restrict__ fc_w)
{
    __shared__ float asm_[64][33];  // [b][red-step]
    __shared__ float bsm[64][65];   // weight: [h-step][k] (32x65 used); x: [k][i-step] (64x33 used)
    const int k0  = blockIdx.x * 64;
    const int seg = blockIdx.y;
    const int tid = threadIdx.x;
    const int tx  = tid & 15;       // k quad
    const int ty  = tid >> 4;       // b quad

    float acc[4][4];
#pragma unroll
    for (int i = 0; i < 4; ++i)
#pragma unroll
        for (int j = 0; j < 4; ++j) acc[i][j] = 0.f;

    if (seg < WSEG) {
        // ---- h_pre @ weight over h in [seg*128, seg*128+128) ----
        for (int step = 0; step < 4; ++step) {
            const int hh0 = seg * 128 + step * 32;
            __syncthreads();
#pragma unroll
            for (int r = 0; r < 8; ++r) {
                int idx = tid + r * 256;
                int row = idx >> 5;     // 0..63 (b)
                int col = idx & 31;     // 0..31 (h)
                asm_[row][col] = h_pre[row * HH + hh0 + col];
            }
#pragma unroll
            for (int r = 0; r < 8; ++r) {
                int idx = tid + r * 256;
                int row = idx >> 6;     // 0..31 (h)
                int col = idx & 63;     // 0..63 (k)
                bsm[row][col] = weight[(hh0 + row) * HH + k0 + col];
            }
            __syncthreads();
#pragma unroll
            for (int ii = 0; ii < 32; ++ii) {
                float xv[4], wv[4];
#pragma unroll
                for (int q = 0; q < 4; ++q) { xv[q] = asm_[ty * 4 + q][ii]; wv[q] = bsm[ii][tx * 4 + q]; }
#pragma unroll
                for (int bi = 0; bi < 4; ++bi)
#pragma unroll
                    for (int ki = 0; ki < 4; ++ki)
                        acc[bi][ki] = fmaf(xv[bi], wv[ki], acc[bi][ki]);
            }
        }
    } else {
        // ---- x @ fc_w^T over i in [(seg-WSEG)*128, +128) ----
        const int xs = seg - WSEG;
        float (*wsm)[33] = reinterpret_cast<float (*)[33]>(&bsm[0][0]); // 64x33 view
        for (int step = 0; step < 4; ++step) {
            const int ii0 = xs * 128 + step * 32;
            __syncthreads();
#pragma unroll
            for (int r = 0; r < 8; ++r) {
                int idx = tid + r * 256;
                int row = idx >> 5;     // 0..63
                int col = idx & 31;     // 0..31
                asm_[row][col] = x[row * II + ii0 + col];
                wsm[row][col]  = fc_w[(k0 + row) * II + ii0 + col];
            }
            __syncthreads();
#pragma unroll
            for (int ii = 0; ii < 32; ++ii) {
                float xv[4], wv[4];
#pragma unroll
                for (int q = 0; q < 4; ++q) { xv[q] = asm_[ty * 4 + q][ii]; wv[q] = wsm[tx * 4 + q][ii]; }
#pragma unroll
                for (int bi = 0; bi < 4; ++bi)
#pragma unroll
                    for (int ki = 0; ki < 4; ++ki)
                        acc[bi][ki] = fmaf(xv[bi], wv[ki], acc[bi][ki]);
            }
        }
    }

#pragma unroll
    for (int bi = 0; bi < 4; ++bi) {
        float4 v = make_float4(acc[bi][0], acc[bi][1], acc[bi][2], acc[bi][3]);
        atomicAdd(reinterpret_cast<float4*>(&g_pre[ty * 4 + bi][k0 + tx * 4]), v);
    }
}

// ---------------------------------------------------------------------------
// Kernel B2: per-batch LN + tanh + m + etah.
// Reads g_pre (+fc_b here, not pre-accumulated), then ZEROES g_pre to
// restore the accumulate-from-zero invariant for the next graph replay.
// ---------------------------------------------------------------------------
__device__ __forceinline__ float block_reduce_sum(float v, float* sred, int tid)
{
#pragma unroll
    for (int o = 16; o > 0; o >>= 1) v += __shfl_down_sync(0xffffffffu, v, o);
    if ((tid & 31) == 0) sred[tid >> 5] = v;
    __syncthreads();
    if (tid < 8) {
        float x = sred[tid];
#pragma unroll
        for (int o = 4; o > 0; o >>= 1) x += __shfl_down_sync(0xffu, x, o);
        if (tid == 0) sred[0] = x;
    }
    __syncthreads();
    float r = sred[0];
    __syncthreads();   // protect sred for next reduction
    return r;
}

__global__ __launch_bounds__(256) void ln_mod_kernel(
    const float* __restrict__ fc_b,
    const float* __restrict__ ln_g,  const float* __restrict__ ln_b,
    const float* __restrict__ mod_w, const float* __restrict__ mod_b,
    const float* __restrict__ modf_w, const float* __restrict__ modf_b,
    float* __restrict__ out_hpost, float* __restrict__ out_m)
{
    const int b   = blockIdx.x;
    const int tid = threadIdx.x;
    __shared__ float sred[8];
    __shared__ float sm;

    float4 v  = reinterpret_cast<const float4*>(&g_pre[b][0])[tid];
    float4 fb = reinterpret_cast<const float4*>(fc_b)[tid];
    v.x += fb.x; v.y += fb.y; v.z += fb.z; v.w += fb.w;

    // restore g_pre = 0 for the next replay
    reinterpret_cast<float4*>(&g_pre[b][0])[tid] = make_float4(0.f, 0.f, 0.f, 0.f);

    float s  = v.x + v.y + v.z + v.w;
    float s2 = v.x * v.x + v.y * v.y + v.z * v.z + v.w * v.w;
    s  = block_reduce_sum(s,  sred, tid);
    s2 = block_reduce_sum(s2, sred, tid);
    const float mu   = s / (float)HH;
    const float var  = s2 / (float)HH - mu * mu;
    const float rstd = rsqrtf(var + LN_EPS);

    float4 g  = reinterpret_cast<const float4*>(ln_g)[tid];
    float4 be = reinterpret_cast<const float4*>(ln_b)[tid];
    float4 hp;
    hp.x = tanhf((v.x - mu) * rstd * g.x + be.x);
    hp.y = tanhf((v.y - mu) * rstd * g.y + be.y);
    hp.z = tanhf((v.z - mu) * rstd * g.z + be.z);
    hp.w = tanhf((v.w - mu) * rstd * g.w + be.w);
    reinterpret_cast<float4*>(out_hpost + b * HH)[tid] = hp;

    // m = tanh(dot(h_post, mod_w) + mod_b)
    float4 mw = reinterpret_cast<const float4*>(mod_w)[tid];
    float d = hp.x * mw.x + hp.y * mw.y + hp.z * mw.z + hp.w * mw.w;
    d = block_reduce_sum(d, sred, tid);
    if (tid == 0) {
        float m = tanhf(d + mod_b[0]);
        out_m[b] = m;
        sm = m;
    }
    __syncthreads();
    const float m = sm;

    // etah[b,k] = (m*modf_w[k] + modf_b[k]) * h_post[b,k]
    float4 fw  = reinterpret_cast<const float4*>(modf_w)[tid];
    float4 fbb = reinterpret_cast<const float4*>(modf_b)[tid];
    float4 t;
    t.x = fmaf(m, fw.x, fbb.x) * hp.x;
    t.y = fmaf(m, fw.y, fbb.y) * hp.y;
    t.z = fmaf(m, fw.z, fbb.z) * hp.z;
    t.w = fmaf(m, fw.w, fbb.w) * hp.w;
    reinterpret_cast<float4*>(&g_etah[b][0])[tid] = t;
}

// ---------------------------------------------------------------------------
// Kernel C: hebb_new[b,h,k] = clip(hebb[b,h,k] + h_pre[b,h]*etah[b,k])
// Measured at ~76% of HBM spec across rounds (practical ceiling); unchanged.
// ---------------------------------------------------------------------------
__global__ __launch_bounds__(256) void hebb_update_kernel(
    const float* __restrict__ h_pre, const float* __restrict__ hebb,
    float* __restrict__ out_hebb)
{
    const int row0 = blockIdx.x * CROWS;
    const int tid  = threadIdx.x;
#pragma unroll
    for (int r = 0; r < CROWS; ++r) {
        const int bh = row0 + r;
        const int b  = bh >> 10;
        const float hpv = __ldg(&h_pre[bh]);   // h_pre[b*H + h] == h_pre[bh]
        const float4 e = ldcs4(reinterpret_cast<const float4*>(hebb) + bh * (HH / 4) + tid);
        const float4 t = reinterpret_cast<const float4*>(&g_etah[b][0])[tid];
        float4 o;
        o.x = fminf(fmaxf(fmaf(hpv, t.x, e.x), -CLIPV), CLIPV);
        o.y = fminf(fmaxf(fmaf(hpv, t.y, e.y), -CLIPV), CLIPV);
        o.z = fminf(fmaxf(fmaf(hpv, t.z, e.z), -CLIPV), CLIPV);
        o.w = fminf(fmaxf(fmaf(hpv, t.w, e.w), -CLIPV), CLIPV);
        stcs4(reinterpret_cast<float4*>(out_hebb) + bh * (HH / 4) + tid, o);
    }
}

// ---------------------------------------------------------------------------
// Launch. Inputs in metadata order:
// 0 x, 1 h_pre, 2 hebb, 3 fc_w, 4 fc_b, 5 weight, 6 alpha,
// 7 ln_g, 8 ln_b, 9 mod_w, 10 mod_b, 11 modf_w, 12 modf_b
// Output: h_post [64*1024] | m [64] | hebb_new [64*1024*1024], fp32.
// ---------------------------------------------------------------------------
extern "C" void kernel_launch(void* const* d_in, const int* in_sizes, int n_in,
                              void* d_out, int out_size)
{
    const float* x      = (const float*)d_in[0];
    const float* h_pre  = (const float*)d_in[1];
    const float* hebb   = (const float*)d_in[2];
    const float* fc_w   = (const float*)d_in[3];
    const float* fc_b   = (const float*)d_in[4];
    const float* weight = (const float*)d_in[5];
    const float* alpha  = (const float*)d_in[6];
    const float* ln_g   = (const float*)d_in[7];
    const float* ln_b   = (const float*)d_in[8];
    const float* mod_w  = (const float*)d_in[9];
    const float* mod_b  = (const float*)d_in[10];
    const float* modf_w = (const float*)d_in[11];
    const float* modf_b = (const float*)d_in[12];

    float* out       = (float*)d_out;
    float* out_hpost = out;                 // 64*1024
    float* out_m     = out + BB * HH;       // 64
    float* out_hebb  = out + BB * HH + BB;  // 64*1024*1024

    rec_partial_kernel<<<dim3(NCHUNK, BGROUPS), 256>>>(h_pre, hebb, alpha);
    gemm_all_kernel<<<dim3(HH / 64, WSEG + XSEG), 256>>>(h_pre, weight, x, fc_w);
    ln_mod_kernel<<<BB, 256>>>(fc_b, ln_g, ln_b, mod_w, mod_b, modf_w, modf_b,
                               out_hpost, out_m);
    hebb_update_kernel<<<(BB * HH) / CROWS, 256>>>(h_pre, hebb, out_hebb);
}

// round 16
// speedup vs baseline: 1.3041x; 1.0267x over previous
#include <cuda_runtime.h>

#define BB 64
#define II 512
#define HH 1024
#define NCHUNK 32              // h-dimension split for rec partials
#define HCHUNK (HH / NCHUNK)   // 32
#define BTILE 8                // batches per block in rec kernel
#define BGROUPS (BB / BTILE)   // 8
#define CROWS 8                // (b,h) rows per block in hebb update
#define WSEG 16                // K-segments for h_pre@weight (K=64 each)
#define XSEG 8                 // K-segments for x@fc_w^T   (K=64 each)
#define CLIPV 2.0f
#define LN_EPS 1e-5f

// Scratch (no allocations allowed -> __device__ globals)
// g_pre invariant: ZERO at kernel_launch entry. Zero-initialized at module
// load; ln_mod_kernel re-zeroes it after reading, restoring the invariant
// for the next graph replay.
__device__ float g_pre[BB][HH];    // atomic accumulator (rec + both gemms)
__device__ float g_etah[BB][HH];   // eta * h_post

__device__ __forceinline__ float4 ldcs4(const float4* p)
{
    float4 v;
    asm volatile("ld.global.cs.v4.f32 {%0,%1,%2,%3}, [%4];"
                 : "=f"(v.x), "=f"(v.y), "=f"(v.z), "=f"(v.w) : "l"(p));
    return v;
}

__device__ __forceinline__ void stcs4(float4* p, float4 v)
{
    asm volatile("st.global.cs.v4.f32 [%0], {%1,%2,%3,%4};"
                 :: "l"(p), "f"(v.x), "f"(v.y), "f"(v.z), "f"(v.w));
}

// ---------------------------------------------------------------------------
// Kernel A: rec hebb contribution, atomically accumulated into g_pre.
// g_pre[b][k] += sum_{h in chunk} h_pre[b,h] * alpha[h,k] * hebb[b,h,k]
// R16: BTILE 4->8 halves alpha re-reads: LTS = 268 hebb + 32 alpha + 8
// atomics = 308 MB (~47us at the 6.8 TB/s LTS rate hebb_update achieves).
// lb(256,2) -> ~96 regs, 16 warps/SM; in-flight bytes/SM ~64 KB >> ~27 KB
// latency-BW product, so 16 warps suffice. Grid = 32 x 8 = 256 blocks.
// ---------------------------------------------------------------------------
__global__ __launch_bounds__(256, 2) void rec_partial_kernel(
    const float* __restrict__ h_pre, const float* __restrict__ hebb,
    const float* __restrict__ alpha)
{
    const int chunk = blockIdx.x;        // 0..NCHUNK-1
    const int bg    = blockIdx.y;        // 0..BGROUPS-1
    const int tid   = threadIdx.x;       // 0..255 -> float4 lane over k
    const int b0    = bg * BTILE;
    const int h0    = chunk * HCHUNK;

    __shared__ float hp[BTILE][HCHUNK];
    {
        int j  = tid >> 5;               // 0..7
        int hh = tid & 31;               // 0..31
        hp[j][hh] = h_pre[(b0 + j) * HH + h0 + hh];
    }
    __syncthreads();

    const float4* a4 = reinterpret_cast<const float4*>(alpha);
    const float4* e4 = reinterpret_cast<const float4*>(hebb);

    float4 acc[BTILE];
#pragma unroll
    for (int j = 0; j < BTILE; ++j) acc[j] = make_float4(0.f, 0.f, 0.f, 0.f);

    const float4* pj[BTILE];
#pragma unroll
    for (int j = 0; j < BTILE; ++j)
        pj[j] = e4 + ((b0 + j) * HH + h0) * (HH / 4) + tid;

#pragma unroll 2
    for (int hi = 0; hi < HCHUNK; ++hi) {
        const int h = h0 + hi;
        const float4 a = a4[h * (HH / 4) + tid];
        float4 e[BTILE];
#pragma unroll
        for (int j = 0; j < BTILE; ++j)
            e[j] = ldcs4(pj[j] + hi * (HH / 4));
#pragma unroll
        for (int j = 0; j < BTILE; ++j) {
            const float s = hp[j][hi];
            acc[j].x = fmaf(s * a.x, e[j].x, acc[j].x);
            acc[j].y = fmaf(s * a.y, e[j].y, acc[j].y);
            acc[j].z = fmaf(s * a.z, e[j].z, acc[j].z);
            acc[j].w = fmaf(s * a.w, e[j].w, acc[j].w);
        }
    }

#pragma unroll
    for (int j = 0; j < BTILE; ++j)
        atomicAdd(reinterpret_cast<float4*>(&g_pre[b0 + j][0]) + tid, acc[j]);
}

// ---------------------------------------------------------------------------
// Kernel G: BOTH small GEMMs in one launch, K-split doubled (K=64/block,
// 2 serial smem steps -> half the per-block critical path of R15).
// blockIdx.y = seg: 0..WSEG-1     -> g_pre += h_pre[:, seg*64:+64] @ weight
//              WSEG..WSEG+XSEG-1  -> g_pre += x[:, s*64:+64] @ fc_w^T
// Register-tiled 64b x 64k, 4x4 out/thread, atomic float4 epilogue.
// Grid 16 x 24 = 384 blocks.
// ---------------------------------------------------------------------------
__global__ __launch_bounds__(256) void gemm_all_kernel(
    const float* __restrict__ h_pre, const float* __restrict__ weight,
    const float* __restrict__ x, const float* __restrict__ fc_w)
{
    __shared__ float asm_[64][33];  // [b][red-step]
    __shared__ float bsm[64][65];   // weight: [h-step][k] (32x65 used); x: [k][i-step] (64x33 used)
    const int k0  = blockIdx.x * 64;
    const int seg = blockIdx.y;
    const int tid = threadIdx.x;
    const int tx  = tid & 15;       // k quad
    const int ty  = tid >> 4;       // b quad

    float acc[4][4];
#pragma unroll
    for (int i = 0; i < 4; ++i)
#pragma unroll
        for (int j = 0; j < 4; ++j) acc[i][j] = 0.f;

    if (seg < WSEG) {
        // ---- h_pre @ weight over h in [seg*64, seg*64+64) ----
        for (int step = 0; step < 2; ++step) {
            const int hh0 = seg * 64 + step * 32;
            __syncthreads();
#pragma unroll
            for (int r = 0; r < 8; ++r) {
                int idx = tid + r * 256;
                int row = idx >> 5;     // 0..63 (b)
                int col = idx & 31;     // 0..31 (h)
                asm_[row][col] = h_pre[row * HH + hh0 + col];
            }
#pragma unroll
            for (int r = 0; r < 8; ++r) {
                int idx = tid + r * 256;
                int row = idx >> 6;     // 0..31 (h)
                int col = idx & 63;     // 0..63 (k)
                bsm[row][col] = weight[(hh0 + row) * HH + k0 + col];
            }
            __syncthreads();
#pragma unroll
            for (int ii = 0; ii < 32; ++ii) {
                float xv[4], wv[4];
#pragma unroll
                for (int q = 0; q < 4; ++q) { xv[q] = asm_[ty * 4 + q][ii]; wv[q] = bsm[ii][tx * 4 + q]; }
#pragma unroll
                for (int bi = 0; bi < 4; ++bi)
#pragma unroll
                    for (int ki = 0; ki < 4; ++ki)
                        acc[bi][ki] = fmaf(xv[bi], wv[ki], acc[bi][ki]);
            }
        }
    } else {
        // ---- x @ fc_w^T over i in [(seg-WSEG)*64, +64) ----
        const int xs = seg - WSEG;
        float (*wsm)[33] = reinterpret_cast<float (*)[33]>(&bsm[0][0]); // 64x33 view
        for (int step = 0; step < 2; ++step) {
            const int ii0 = xs * 64 + step * 32;
            __syncthreads();
#pragma unroll
            for (int r = 0; r < 8; ++r) {
                int idx = tid + r * 256;
                int row = idx >> 5;     // 0..63
                int col = idx & 31;     // 0..31
                asm_[row][col] = x[row * II + ii0 + col];
                wsm[row][col]  = fc_w[(k0 + row) * II + ii0 + col];
            }
            __syncthreads();
#pragma unroll
            for (int ii = 0; ii < 32; ++ii) {
                float xv[4], wv[4];
#pragma unroll
                for (int q = 0; q < 4; ++q) { xv[q] = asm_[ty * 4 + q][ii]; wv[q] = wsm[tx * 4 + q][ii]; }
#pragma unroll
                for (int bi = 0; bi < 4; ++bi)
#pragma unroll
                    for (int ki = 0; ki < 4; ++ki)
                        acc[bi][ki] = fmaf(xv[bi], wv[ki], acc[bi][ki]);
            }
        }
    }

#pragma unroll
    for (int bi = 0; bi < 4; ++bi) {
        float4 v = make_float4(acc[bi][0], acc[bi][1], acc[bi][2], acc[bi][3]);
        atomicAdd(reinterpret_cast<float4*>(&g_pre[ty * 4 + bi][k0 + tx * 4]), v);
    }
}

// ---------------------------------------------------------------------------
// Kernel B2: per-batch LN + tanh + m + etah.
// Reads g_pre (+fc_b here), then ZEROES g_pre to restore the
// accumulate-from-zero invariant for the next graph replay.
// ---------------------------------------------------------------------------
__device__ __forceinline__ float block_reduce_sum(float v, float* sred, int tid)
{
#pragma unroll
    for (int o = 16; o > 0; o >>= 1) v += __shfl_down_sync(0xffffffffu, v, o);
    if ((tid & 31) == 0) sred[tid >> 5] = v;
    __syncthreads();
    if (tid < 8) {
        float x = sred[tid];
#pragma unroll
        for (int o = 4; o > 0; o >>= 1) x += __shfl_down_sync(0xffu, x, o);
        if (tid == 0) sred[0] = x;
    }
    __syncthreads();
    float r = sred[0];
    __syncthreads();   // protect sred for next reduction
    return r;
}

__global__ __launch_bounds__(256) void ln_mod_kernel(
    const float* __restrict__ fc_b,
    const float* __restrict__ ln_g,  const float* __restrict__ ln_b,
    const float* __restrict__ mod_w, const float* __restrict__ mod_b,
    const float* __restrict__ modf_w, const float* __restrict__ modf_b,
    float* __restrict__ out_hpost, float* __restrict__ out_m)
{
    const int b   = blockIdx.x;
    const int tid = threadIdx.x;
    __shared__ float sred[8];
    __shared__ float sm;

    float4 v  = reinterpret_cast<const float4*>(&g_pre[b][0])[tid];
    float4 fb = reinterpret_cast<const float4*>(fc_b)[tid];
    v.x += fb.x; v.y += fb.y; v.z += fb.z; v.w += fb.w;

    // restore g_pre = 0 for the next replay
    reinterpret_cast<float4*>(&g_pre[b][0])[tid] = make_float4(0.f, 0.f, 0.f, 0.f);

    float s  = v.x + v.y + v.z + v.w;
    float s2 = v.x * v.x + v.y * v.y + v.z * v.z + v.w * v.w;
    s  = block_reduce_sum(s,  sred, tid);
    s2 = block_reduce_sum(s2, sred, tid);
    const float mu   = s / (float)HH;
    const float var  = s2 / (float)HH - mu * mu;
    const float rstd = rsqrtf(var + LN_EPS);

    float4 g  = reinterpret_cast<const float4*>(ln_g)[tid];
    float4 be = reinterpret_cast<const float4*>(ln_b)[tid];
    float4 hp;
    hp.x = tanhf((v.x - mu) * rstd * g.x + be.x);
    hp.y = tanhf((v.y - mu) * rstd * g.y + be.y);
    hp.z = tanhf((v.z - mu) * rstd * g.z + be.z);
    hp.w = tanhf((v.w - mu) * rstd * g.w + be.w);
    reinterpret_cast<float4*>(out_hpost + b * HH)[tid] = hp;

    // m = tanh(dot(h_post, mod_w) + mod_b)
    float4 mw = reinterpret_cast<const float4*>(mod_w)[tid];
    float d = hp.x * mw.x + hp.y * mw.y + hp.z * mw.z + hp.w * mw.w;
    d = block_reduce_sum(d, sred, tid);
    if (tid == 0) {
        float m = tanhf(d + mod_b[0]);
        out_m[b] = m;
        sm = m;
    }
    __syncthreads();
    const float m = sm;

    // etah[b,k] = (m*modf_w[k] + modf_b[k]) * h_post[b,k]
    float4 fw  = reinterpret_cast<const float4*>(modf_w)[tid];
    float4 fbb = reinterpret_cast<const float4*>(modf_b)[tid];
    float4 t;
    t.x = fmaf(m, fw.x, fbb.x) * hp.x;
    t.y = fmaf(m, fw.y, fbb.y) * hp.y;
    t.z = fmaf(m, fw.z, fbb.z) * hp.z;
    t.w = fmaf(m, fw.w, fbb.w) * hp.w;
    reinterpret_cast<float4*>(&g_etah[b][0])[tid] = t;
}

// ---------------------------------------------------------------------------
// Kernel C: hebb_new[b,h,k] = clip(hebb[b,h,k] + h_pre[b,h]*etah[b,k])
// Measured at ~77% of HBM spec across rounds (practical ceiling); unchanged.
// ---------------------------------------------------------------------------
__global__ __launch_bounds__(256) void hebb_update_kernel(
    const float* __restrict__ h_pre, const float* __restrict__ hebb,
    float* __restrict__ out_hebb)
{
    const int row0 = blockIdx.x * CROWS;
    const int tid  = threadIdx.x;
#pragma unroll
    for (int r = 0; r < CROWS; ++r) {
        const int bh = row0 + r;
        const int b  = bh >> 10;
        const float hpv = __ldg(&h_pre[bh]);   // h_pre[b*H + h] == h_pre[bh]
        const float4 e = ldcs4(reinterpret_cast<const float4*>(hebb) + bh * (HH / 4) + tid);
        const float4 t = reinterpret_cast<const float4*>(&g_etah[b][0])[tid];
        float4 o;
        o.x = fminf(fmaxf(fmaf(hpv, t.x, e.x), -CLIPV), CLIPV);
        o.y = fminf(fmaxf(fmaf(hpv, t.y, e.y), -CLIPV), CLIPV);
        o.z = fminf(fmaxf(fmaf(hpv, t.z, e.z), -CLIPV), CLIPV);
        o.w = fminf(fmaxf(fmaf(hpv, t.w, e.w), -CLIPV), CLIPV);
        stcs4(reinterpret_cast<float4*>(out_hebb) + bh * (HH / 4) + tid, o);
    }
}

// ---------------------------------------------------------------------------
// Launch. Inputs in metadata order:
// 0 x, 1 h_pre, 2 hebb, 3 fc_w, 4 fc_b, 5 weight, 6 alpha,
// 7 ln_g, 8 ln_b, 9 mod_w, 10 mod_b, 11 modf_w, 12 modf_b
// Output: h_post [64*1024] | m [64] | hebb_new [64*1024*1024], fp32.
// ---------------------------------------------------------------------------
extern "C" void kernel_launch(void* const* d_in, const int* in_sizes, int n_in,
                              void* d_out, int out_size)
{
    const float* x      = (const float*)d_in[0];
    const float* h_pre  = (const float*)d_in[1];
    const float* hebb   = (const float*)d_in[2];
    const float* fc_w   = (const float*)d_in[3];
    const float* fc_b   = (const float*)d_in[4];
    const float* weight = (const float*)d_in[5];
    const float* alpha  = (const float*)d_in[6];
    const float* ln_g   = (const float*)d_in[7];
    const float* ln_b   = (const float*)d_in[8];
    const float* mod_w  = (const float*)d_in[9];
    const float* mod_b  = (const float*)d_in[10];
    const float* modf_w = (const float*)d_in[11];
    const float* modf_b = (const float*)d_in[12];

    float* out       = (float*)d_out;
    float* out_hpost = out;                 // 64*1024
    float* out_m     = out + BB * HH;       // 64
    float* out_hebb  = out + BB * HH + BB;  // 64*1024*1024

    rec_partial_kernel<<<dim3(NCHUNK, BGROUPS), 256>>>(h_pre, hebb, alpha);
    gemm_all_kernel<<<dim3(HH / 64, WSEG + XSEG), 256>>>(h_pre, weight, x, fc_w);
    ln_mod_kernel<<<BB, 256>>>(fc_b, ln_g, ln_b, mod_w, mod_b, modf_w, modf_b,
                               out_hpost, out_m);
    hebb_update_kernel<<<(BB * HH) / CROWS, 256>>>(h_pre, hebb, out_hebb);
}